// round 15
// baseline (speedup 1.0000x reference)
#include <cuda_runtime.h>
#include <cuda_fp16.h>
#include <cstdint>

#define BATCH 4096
#define SDIM  64
#define OUTD  12
#define BM    128     // batch rows per tile
#define BN    128     // gemm columns per tile (= 2 neurons)

// ---------------- scratch (device globals; no allocs allowed) ----------------
__device__ __align__(256) __half g_ah[BATCH * 512];    // A fp16 (x or h)
__device__ __align__(256) __half g_wth[11010048];      // W^T fp16, all layers
__device__ __align__(256) __half g_preh[BATCH * 256];  // pre (fp16)
__device__ __align__(256) __half g_lat[86016];         // La^T fp16, layers 0,1
__device__ __align__(256) float  g_m2[64 * OUTD];      // La2 @ Wout (f32)

// ---------------- helpers ----------------
__device__ __forceinline__ uint32_t smem_u32(const void* p) {
    uint32_t a;
    asm("{ .reg .u64 t; cvta.to.shared.u64 t, %1; cvt.u32.u64 %0, t; }" : "=r"(a) : "l"(p));
    return a;
}
__device__ __forceinline__ void cp16(uint32_t s, const void* g) {
    asm volatile("cp.async.cg.shared.global [%0], [%1], 16;" :: "r"(s), "l"(g));
}
#define CP_COMMIT() asm volatile("cp.async.commit_group;" ::: "memory")
#define CP_WAIT(n)  asm volatile("cp.async.wait_group %0;" :: "n"(n) : "memory")
#define BAR_SYNC(id, cnt)   asm volatile("bar.sync %0, %1;"   :: "r"(id), "r"(cnt) : "memory")
#define BAR_ARRIVE(id, cnt) asm volatile("bar.arrive %0, %1;" :: "r"(id), "r"(cnt) : "memory")
#define MEMBAR_CTA() asm volatile("membar.cta;" ::: "memory")

__device__ __forceinline__ void ldm_x4(uint32_t* r, uint32_t addr) {
    asm volatile("ldmatrix.sync.aligned.m8n8.x4.shared.b16 {%0,%1,%2,%3}, [%4];"
                 : "=r"(r[0]), "=r"(r[1]), "=r"(r[2]), "=r"(r[3]) : "r"(addr));
}
__device__ __forceinline__ void mma16816(float* d, const uint32_t* a, const uint32_t* b) {
    asm volatile("mma.sync.aligned.m16n8k16.row.col.f32.f16.f16.f32 "
                 "{%0,%1,%2,%3}, {%4,%5,%6,%7}, {%8,%9}, {%0,%1,%2,%3};"
                 : "+f"(d[0]), "+f"(d[1]), "+f"(d[2]), "+f"(d[3])
                 : "r"(a[0]), "r"(a[1]), "r"(a[2]), "r"(a[3]), "r"(b[0]), "r"(b[1]));
}
__device__ __forceinline__ uint32_t swz(uint32_t off) {   // SW128: rows of 128B
    return off ^ ((off >> 3) & 0x70);
}
// activation: tanh(v) + 0.1*sin(0.5v)*cos(0.3v)
__device__ __forceinline__ float liquid_act(float v) {
    float t, s, c;
    asm("tanh.approx.f32 %0, %1;" : "=f"(t) : "f"(v));
    asm("sin.approx.f32 %0, %1;" : "=f"(s) : "f"(0.5f * v));
    asm("cos.approx.f32 %0, %1;" : "=f"(c) : "f"(0.3f * v));
    return t + 0.1f * s * c;
}

// ---------------- warp-specialized GEMM smem layout ----------------
// A stages @0 (3x16KB); B stages @49152 (3x16KB); D @98304 (128x132 f32 = 67584);
// bias @165888 (128 f32); wo @166400 (128 f32)
#define WS_B_OFF  49152
#define WS_D_OFF  98304
#define WS_DPITCH 132
#define WS_BS     165888
#define WS_WS     166400
#define WS_TOTAL  166912

#define FILL_BAR 1
#define FREE_BAR 2
#define PROD_BAR 3
#define CONS_BAR 4

// Persistent warp-specialized GEMM: warps 0-7 = HMMA producers (warp tile 64x32),
// warps 8-11 = activation/Wo-dot consumers reading D from smem.
__global__ void __launch_bounds__(384, 1)
liquid_ws_kernel(const __half* __restrict__ Ah, const __half* __restrict__ Bth,
                 const float* __restrict__ bi, const float* __restrict__ bl,
                 const float* __restrict__ Wo, const float* __restrict__ bo,
                 __half* __restrict__ preh, int K, int Nn, int ntiles, int nbx)
{
    extern __shared__ char smem[];
    const uint32_t sb = smem_u32(smem);
    float* Dsm = (float*)(smem + WS_D_OFF);
    float* bs  = (float*)(smem + WS_BS);
    float* ws  = (float*)(smem + WS_WS);
    const int tid = threadIdx.x;
    const int wid = tid >> 5;
    const int lane = tid & 31;
    const int niters = K >> 6;

    if (wid < 8) {
        // ================= PRODUCER =================
        const int wm = wid >> 2;          // 0-1
        const int wn = wid & 3;           // 0-3 -> 32-col slice
        const int lrow = tid >> 3;        // 0..31 (256 prod threads)
        const int lseg = tid & 7;
        const int a_row = wm * 64 + (lane & 15);
        const int a_cb  = (lane >> 4) * 16;
        const int b_row = wn * 32 + (lane & 7) + ((lane >> 4) << 3);
        const int b_cb  = ((lane >> 3) & 1) * 16;

        auto issue_chunk = [&](int tb0, int tc0, int k0, int st) {
            uint32_t sA = sb + st * 16384;
            uint32_t sB = sb + WS_B_OFF + st * 16384;
            #pragma unroll
            for (int i = 0; i < 4; ++i) {
                int row = lrow + i * 32;
                uint32_t so = swz(row * 128 + lseg * 16);
                cp16(sA + so, Ah  + (size_t)(tb0 + row) * K + k0 + lseg * 8);
                cp16(sB + so, Bth + (size_t)(tc0 + row) * K + k0 + lseg * 8);
            }
            CP_COMMIT();
        };

        int tile = blockIdx.x;
        int bx = tile % nbx, by = tile / nbx;
        int b0 = bx * BM, c0 = by * BN;
        int st_fill = 0, st_use = 0;
        issue_chunk(b0, c0, 0, 0); st_fill = 1;
        if (niters > 1) { issue_chunk(b0, c0, 64, 1); st_fill = 2; }

        while (tile < ntiles) {
            const int next_tile = tile + gridDim.x;
            const bool has_next = next_tile < ntiles;
            const int nbx2 = next_tile % nbx, nby2 = next_tile / nbx;
            const int nb0 = nbx2 * BM, nc0 = nby2 * BN;

            float d[4][4][4];
            #pragma unroll
            for (int mi = 0; mi < 4; ++mi)
                #pragma unroll
                for (int nj = 0; nj < 4; ++nj)
                    #pragma unroll
                    for (int c = 0; c < 4; ++c) d[mi][nj][c] = 0.f;

            for (int it = 0; it < niters; ++it) {
                if (it == niters - 1 && !has_next) { CP_WAIT(0); } else { CP_WAIT(1); }
                BAR_SYNC(PROD_BAR, 256);
                int ahead = it + 2;
                if (ahead < niters) {
                    issue_chunk(b0, c0, ahead << 6, st_fill);
                    st_fill = (st_fill == 2) ? 0 : st_fill + 1;
                } else if (has_next && ahead - niters < 2) {
                    issue_chunk(nb0, nc0, (ahead - niters) << 6, st_fill);
                    st_fill = (st_fill == 2) ? 0 : st_fill + 1;
                }

                uint32_t sA = sb + st_use * 16384;
                uint32_t sB = sb + WS_B_OFF + st_use * 16384;
                #pragma unroll
                for (int ks = 0; ks < 4; ++ks) {
                    uint32_t afr[4][4], bfr[2][4];
                    #pragma unroll
                    for (int mi = 0; mi < 4; ++mi)
                        ldm_x4(afr[mi], sA + swz((a_row + mi * 16) * 128 + ks * 32 + a_cb));
                    #pragma unroll
                    for (int nj2 = 0; nj2 < 2; ++nj2)
                        ldm_x4(bfr[nj2], sB + swz((b_row + nj2 * 16) * 128 + ks * 32 + b_cb));
                    #pragma unroll
                    for (int mi = 0; mi < 4; ++mi)
                        #pragma unroll
                        for (int nj = 0; nj < 4; ++nj)
                            mma16816(d[mi][nj], afr[mi], &bfr[nj >> 1][(nj & 1) * 2]);
                }
                st_use = (st_use == 2) ? 0 : st_use + 1;
            }

            // wait D buffer free, store D, signal filled
            BAR_SYNC(FREE_BAR, 384);
            {
                const int g = lane >> 2, i = lane & 3;
                #pragma unroll
                for (int mi = 0; mi < 4; ++mi) {
                    #pragma unroll
                    for (int nj = 0; nj < 4; ++nj) {
                        int r0 = wm * 64 + mi * 16 + g;
                        int c  = wn * 32 + nj * 8 + 2 * i;
                        *(float2*)(Dsm + r0 * WS_DPITCH + c)       = make_float2(d[mi][nj][0], d[mi][nj][1]);
                        *(float2*)(Dsm + (r0 + 8) * WS_DPITCH + c) = make_float2(d[mi][nj][2], d[mi][nj][3]);
                    }
                }
            }
            MEMBAR_CTA();
            BAR_ARRIVE(FILL_BAR, 384);

            tile = next_tile; b0 = nb0; c0 = nc0; by = nby2;
        }
    } else {
        // ================= CONSUMER =================
        const int ctid = tid - 256;       // 0..127
        int tile = blockIdx.x;
        BAR_ARRIVE(FREE_BAR, 384);        // buffer starts free

        while (tile < ntiles) {
            const int by = tile / nbx;
            const int b0 = (tile % nbx) * BM;
            const int c0 = by * BN;

            BAR_SYNC(CONS_BAR, 128);      // prior epilogue done reading bs/ws
            {
                int gc = c0 + ctid;
                int nn = gc >> 6, s = gc & 63;
                bs[ctid] = bi[nn * SDIM + s] + bl[nn * SDIM + s];
                ws[ctid] = Wo[nn * SDIM + s];
            }
            float bo0 = bo[2 * by], bo1 = bo[2 * by + 1];
            BAR_SYNC(CONS_BAR, 128);      // bs/ws visible to all consumers
            BAR_SYNC(FILL_BAR, 384);      // D filled

            const float* Drow = Dsm + ctid * WS_DPITCH;
            float p0 = 0.f, p1 = 0.f;
            #pragma unroll
            for (int k = 0; k < 16; ++k) {
                float4 v = *(const float4*)(Drow + 4 * k);
                p0 += liquid_act(v.x + bs[4*k])   * ws[4*k];
                p0 += liquid_act(v.y + bs[4*k+1]) * ws[4*k+1];
                p0 += liquid_act(v.z + bs[4*k+2]) * ws[4*k+2];
                p0 += liquid_act(v.w + bs[4*k+3]) * ws[4*k+3];
            }
            #pragma unroll
            for (int k = 16; k < 32; ++k) {
                float4 v = *(const float4*)(Drow + 4 * k);
                p1 += liquid_act(v.x + bs[4*k])   * ws[4*k];
                p1 += liquid_act(v.y + bs[4*k+1]) * ws[4*k+1];
                p1 += liquid_act(v.z + bs[4*k+2]) * ws[4*k+2];
                p1 += liquid_act(v.w + bs[4*k+3]) * ws[4*k+3];
            }
            int r = b0 + ctid;
            preh[(size_t)r * Nn + 2 * by]     = __float2half(p0 + bo0);
            preh[(size_t)r * Nn + 2 * by + 1] = __float2half(p1 + bo1);

            BAR_ARRIVE(FREE_BAR, 384);    // buffer free for next tile
            tile += gridDim.x;
        }
    }
}

// ---------------- lateral GEMM (layers 0,1): hh[b][n] = sum_m preh[b][m]*La[m][n] ----------------
#define LSM_B_OFF 49152
#define LSM_TOTAL 73728
__global__ void __launch_bounds__(128, 2)
lat_mma_kernel(const __half* __restrict__ preh, const __half* __restrict__ Lat,
               __half* __restrict__ hh, int N)
{
    extern __shared__ char smem[];
    const uint32_t sb = smem_u32(smem);
    const int tid = threadIdx.x;
    const int wid  = tid >> 5;
    const int lane = tid & 31;
    const int wm = wid >> 1;
    const int wn = wid & 1;
    const int b0 = blockIdx.x * 128;
    const int c0 = blockIdx.y * 64;

    float d[4][4][4];
    #pragma unroll
    for (int mi = 0; mi < 4; ++mi)
        #pragma unroll
        for (int nj = 0; nj < 4; ++nj)
            #pragma unroll
            for (int c = 0; c < 4; ++c) d[mi][nj][c] = 0.f;

    const int niters = N >> 6;
    const int lrow = tid >> 3;
    const int lseg = tid & 7;
    const int a_row = wm * 64 + (lane & 15);
    const int a_cb  = (lane >> 4) * 16;
    const int b_row = wn * 32 + (lane & 7) + ((lane >> 4) << 3);
    const int b_cb  = ((lane >> 3) & 1) * 16;

    auto issue_loads = [&](int it, int st) {
        const int k0 = it << 6;
        uint32_t sA = sb + st * 16384;
        uint32_t sB = sb + LSM_B_OFF + st * 8192;
        #pragma unroll
        for (int i = 0; i < 8; ++i) {
            int row = lrow + i * 16;
            uint32_t so = swz(row * 128 + lseg * 16);
            cp16(sA + so, preh + (size_t)(b0 + row) * N + k0 + lseg * 8);
        }
        #pragma unroll
        for (int i = 0; i < 4; ++i) {
            int c = tid + i * 128;
            int row = c >> 3, seg = c & 7;
            uint32_t so = swz(row * 128 + seg * 16);
            cp16(sB + so, Lat + (size_t)(c0 + row) * N + k0 + seg * 8);
        }
        CP_COMMIT();
    };

    issue_loads(0, 0);
    if (niters > 1) issue_loads(1, 1);

    int cur = 0;
    for (int it = 0; it < niters; ++it) {
        if (it == niters - 1) { CP_WAIT(0); } else { CP_WAIT(1); }
        __syncthreads();
        if (it + 2 < niters) {
            int nx = cur + 2; if (nx >= 3) nx -= 3;
            issue_loads(it + 2, nx);
        }

        uint32_t sA = sb + cur * 16384;
        uint32_t sB = sb + LSM_B_OFF + cur * 8192;
        #pragma unroll
        for (int ks = 0; ks < 4; ++ks) {
            uint32_t afr[4][4], bfr[2][4];
            #pragma unroll
            for (int mi = 0; mi < 4; ++mi)
                ldm_x4(afr[mi], sA + swz((a_row + mi * 16) * 128 + ks * 32 + a_cb));
            #pragma unroll
            for (int nj2 = 0; nj2 < 2; ++nj2)
                ldm_x4(bfr[nj2], sB + swz((b_row + nj2 * 16) * 128 + ks * 32 + b_cb));
            #pragma unroll
            for (int mi = 0; mi < 4; ++mi)
                #pragma unroll
                for (int nj = 0; nj < 4; ++nj)
                    mma16816(d[mi][nj], afr[mi], &bfr[nj >> 1][(nj & 1) * 2]);
        }
        cur = (cur == 2) ? 0 : cur + 1;
    }

    {
        const int g = lane >> 2, i = lane & 3;
        #pragma unroll
        for (int mi = 0; mi < 4; ++mi) {
            #pragma unroll
            for (int nj = 0; nj < 4; ++nj) {
                int c = c0 + wn * 32 + nj * 8 + 2 * i;
                int r = b0 + wm * 64 + mi * 16 + g;
                *(__half2*)(hh + (size_t)r * N + c) = __floats2half2_rn(d[mi][nj][0], d[mi][nj][1]);
                *(__half2*)(hh + (size_t)(r + 8) * N + c) = __floats2half2_rn(d[mi][nj][2], d[mi][nj][3]);
            }
        }
    }
}

// ---------------- merged preprocessing: wsplit + latprep(0,1) + xsplit + M2 ----------------
__global__ __launch_bounds__(256)
void prep_all_kernel(const float* __restrict__ Wi0, const float* __restrict__ Wi1,
                     const float* __restrict__ Wi2, __half* __restrict__ wth,
                     const float* __restrict__ L0, const float* __restrict__ a0,
                     const float* __restrict__ L1, const float* __restrict__ a1,
                     __half* __restrict__ lat,
                     const float* __restrict__ L2, const float* __restrict__ a2,
                     const float* __restrict__ Wout, float* __restrict__ m2,
                     const float* __restrict__ x, __half* __restrict__ xh)
{
    int b = blockIdx.x;
    if (b < 2688) {
        const float* Wi; __half* dst; int K, n, kc;
        if (b < 2048)      { Wi = Wi0; dst = wth;            K = 512; kc = b & 7; n = b >> 3; }
        else if (b < 2560) { b -= 2048; Wi = Wi1; dst = wth + 8388608;  K = 256; kc = b & 3; n = b >> 2; }
        else               { b -= 2560; Wi = Wi2; dst = wth + 10485760; K = 128; kc = b & 1; n = b >> 1; }
        const int k0 = kc * 64;
        __shared__ float tile[64][65];
        const float* src = Wi + ((size_t)n * K + k0) * SDIM;
        for (int i = threadIdx.x; i < 4096; i += 256) {
            int kk = i >> 6, s = i & 63;
            tile[kk][s] = src[kk * SDIM + s];
        }
        __syncthreads();
        for (int i = threadIdx.x; i < 4096; i += 256) {
            int s = i >> 6, kk = i & 63;
            dst[(size_t)n * SDIM * K + (size_t)s * K + k0 + kk] = __float2half(tile[kk][s]);
        }
    } else if (b < 3008) {
        b -= 2688;
        const float* L; const float* a; __half* dst; int N;
        if (b < 256) { L = L0; a = a0; dst = lat;         N = 256; }
        else         { b -= 256; L = L1; a = a1; dst = lat + 65536; N = 128; }
        int e = b * 256 + threadIdx.x;
        int n = e / N, k = e - n * N;
        float v = 0.1f * L[(size_t)k * N + n] * a[n];
        if (k == n) v += a[n];
        dst[e] = __float2half(v);
    } else if (b < 5056) {
        int i = (b - 3008) * 256 + threadIdx.x;
        float4 v = ((const float4*)x)[i];
        ((__half2*)xh)[2 * i]     = __floats2half2_rn(v.x, v.y);
        ((__half2*)xh)[2 * i + 1] = __floats2half2_rn(v.z, v.w);
    } else {
        for (int e = threadIdx.x; e < 64 * OUTD; e += 256) {
            int m = e / OUTD, o = e - m * OUTD;
            float s = a2[m] * Wout[m * OUTD + o];
            #pragma unroll 4
            for (int n = 0; n < 64; ++n)
                s += 0.1f * L2[(size_t)m * 64 + n] * a2[n] * Wout[n * OUTD + o];
            m2[e] = s;
        }
    }
}

// ---------------- final projection: y = preh2 @ M2 + bout ----------------
__global__ __launch_bounds__(256)
void out_kernel(const __half* __restrict__ preh, const float* __restrict__ m2,
                const float* __restrict__ bout, float* __restrict__ y)
{
    int idx = blockIdx.x * blockDim.x + threadIdx.x;
    if (idx >= BATCH * OUTD) return;
    int b = idx / OUTD;
    int o = idx - b * OUTD;
    const __half* pb = preh + (size_t)b * 64;
    float s = bout[o];
    #pragma unroll
    for (int m = 0; m < 64; ++m)
        s += __half2float(pb[m]) * m2[m * OUTD + o];
    y[idx] = s;
}

extern "C" void kernel_launch(void* const* d_in, const int* in_sizes, int n_in,
                              void* d_out, int out_size)
{
    (void)in_sizes; (void)n_in; (void)out_size;
    const float* x = (const float*)d_in[0];
    const float *Wi[3], *bi[3], *bl[3], *Wo[3], *bo[3], *Lm[3], *ad[3];
    for (int l = 0; l < 3; ++l) {
        int base = 1 + 7 * l;
        Wi[l] = (const float*)d_in[base + 0];
        bi[l] = (const float*)d_in[base + 1];
        bl[l] = (const float*)d_in[base + 2];
        Wo[l] = (const float*)d_in[base + 3];
        bo[l] = (const float*)d_in[base + 4];
        Lm[l] = (const float*)d_in[base + 5];
        ad[l] = (const float*)d_in[base + 6];
    }
    const float* Wout = (const float*)d_in[22];
    const float* bout = (const float*)d_in[23];

    __half *ah, *wth, *preh, *lat;
    float *m2;
    cudaGetSymbolAddress((void**)&ah,   g_ah);
    cudaGetSymbolAddress((void**)&wth,  g_wth);
    cudaGetSymbolAddress((void**)&preh, g_preh);
    cudaGetSymbolAddress((void**)&lat,  g_lat);
    cudaGetSymbolAddress((void**)&m2,   g_m2);

    cudaFuncSetAttribute(liquid_ws_kernel, cudaFuncAttributeMaxDynamicSharedMemorySize, WS_TOTAL);
    cudaFuncSetAttribute(lat_mma_kernel, cudaFuncAttributeMaxDynamicSharedMemorySize, LSM_TOTAL);

    int nsm = 148;
    cudaDeviceGetAttribute(&nsm, cudaDevAttrMultiProcessorCount, 0);

    const int Ns[3] = {256, 128, 64};
    const int Ks[3] = {512, 256, 128};
    const size_t woff[3] = {0, 8388608, 10485760};
    const size_t loff[2] = {0, 65536};

    prep_all_kernel<<<5057, 256>>>(Wi[0], Wi[1], Wi[2], wth,
                                   Lm[0], ad[0], Lm[1], ad[1], lat,
                                   Lm[2], ad[2], Wout, m2, x, ah);

    for (int l = 0; l < 3; ++l) {
        const int nbx = BATCH / BM;                       // 32
        const int ntiles = nbx * (Ns[l] * SDIM) / BN;     // 4096 / 2048 / 1024
        int grid = nsm < ntiles ? nsm : ntiles;
        liquid_ws_kernel<<<grid, 384, WS_TOTAL>>>(ah, wth + woff[l],
                                                  bi[l], bl[l], Wo[l], bo[l], preh,
                                                  Ks[l], Ns[l], ntiles, nbx);
        if (l < 2) {
            dim3 lgrid(BATCH / 128, Ns[l] / 64);
            lat_mma_kernel<<<lgrid, 128, LSM_TOTAL>>>(preh, lat + loff[l], ah, Ns[l]);
        }
    }
    out_kernel<<<(BATCH * OUTD + 255) / 256, 256>>>(preh, m2, bout, (float*)d_out);
}

// round 16
// speedup vs baseline: 1.1988x; 1.1988x over previous
#include <cuda_runtime.h>
#include <cuda_fp16.h>
#include <cstdint>

#define BATCH 4096
#define SDIM  64
#define OUTD  12
#define BM    128     // batch rows per CTA (main gemm)
#define BN    128     // gemm columns per CTA (= 2 neurons)

// ---------------- scratch (device globals; no allocs allowed) ----------------
__device__ __align__(256) __half g_ah[BATCH * 512];    // A fp16 (x or h)
__device__ __align__(256) __half g_wth[11010048];      // W^T fp16, all layers
__device__ __align__(256) __half g_preh[BATCH * 256];  // pre (fp16)
__device__ __align__(256) __half g_lat[86016];         // La^T fp16, layers 0,1
__device__ __align__(256) float  g_m2[64 * OUTD];      // La2 @ Wout (f32)

// ---------------- helpers ----------------
__device__ __forceinline__ uint32_t smem_u32(const void* p) {
    uint32_t a;
    asm("{ .reg .u64 t; cvta.to.shared.u64 t, %1; cvt.u32.u64 %0, t; }" : "=r"(a) : "l"(p));
    return a;
}
__device__ __forceinline__ void cp16(uint32_t s, const void* g) {
    asm volatile("cp.async.cg.shared.global [%0], [%1], 16;" :: "r"(s), "l"(g));
}
#define CP_COMMIT() asm volatile("cp.async.commit_group;" ::: "memory")
#define CP_WAIT(n)  asm volatile("cp.async.wait_group %0;" :: "n"(n) : "memory")

__device__ __forceinline__ void ldm_x4(uint32_t* r, uint32_t addr) {
    asm volatile("ldmatrix.sync.aligned.m8n8.x4.shared.b16 {%0,%1,%2,%3}, [%4];"
                 : "=r"(r[0]), "=r"(r[1]), "=r"(r[2]), "=r"(r[3]) : "r"(addr));
}
__device__ __forceinline__ void mma16816(float* d, const uint32_t* a, const uint32_t* b) {
    asm volatile("mma.sync.aligned.m16n8k16.row.col.f32.f16.f16.f32 "
                 "{%0,%1,%2,%3}, {%4,%5,%6,%7}, {%8,%9}, {%0,%1,%2,%3};"
                 : "+f"(d[0]), "+f"(d[1]), "+f"(d[2]), "+f"(d[3])
                 : "r"(a[0]), "r"(a[1]), "r"(a[2]), "r"(a[3]), "r"(b[0]), "r"(b[1]));
}
__device__ __forceinline__ uint32_t swz(uint32_t off) {   // SW128: rows of 128B
    return off ^ ((off >> 3) & 0x70);
}
// activation: tanh(v) + 0.1*sin(0.5v)*cos(0.3v)
__device__ __forceinline__ float liquid_act(float v) {
    float t, s, c;
    asm("tanh.approx.f32 %0, %1;" : "=f"(t) : "f"(v));
    asm("sin.approx.f32 %0, %1;" : "=f"(s) : "f"(0.5f * v));
    asm("cos.approx.f32 %0, %1;" : "=f"(c) : "f"(0.3f * v));
    return t + 0.1f * s * c;
}

// smem layout main gemm: A stages @0/16384/32768; B stages @49152/65536/81920;
// bias @98304 (128 f32); wo @98816 (128 f32)
#define SM_B_OFF   49152
#define SM_BIAS    98304
#define SM_WO      98816
#define SM_TOTAL   99328

// Single-pass fp16 HMMA GEMM + fused activation/output-projection epilogue.
// grid: (BATCH/BM, (N*64)/BN), 128 threads = 4 warps, warp tile 64x64.
__global__ void __launch_bounds__(128, 2)
liquid_mma_kernel(const __half* __restrict__ Ah, const __half* __restrict__ Bth,
                  const float* __restrict__ bi, const float* __restrict__ bl,
                  const float* __restrict__ Wo, const float* __restrict__ bo,
                  __half* __restrict__ preh, int K, int Nn)
{
    extern __shared__ char smem[];
    const uint32_t sb = smem_u32(smem);
    const int tid = threadIdx.x;
    const int wid  = tid >> 5;
    const int lane = tid & 31;
    const int wm = wid >> 1;
    const int wn = wid & 1;
    const int b0    = blockIdx.x * BM;
    const int ncol0 = blockIdx.y * BN;

    {
        int gc = ncol0 + tid;
        int nn = gc >> 6, s = gc & 63;
        ((float*)(smem + SM_BIAS))[tid] = bi[nn * SDIM + s] + bl[nn * SDIM + s];
        ((float*)(smem + SM_WO))[tid]   = Wo[nn * SDIM + s];
    }

    float d[4][8][4];
    #pragma unroll
    for (int mi = 0; mi < 4; ++mi)
        #pragma unroll
        for (int nj = 0; nj < 8; ++nj)
            #pragma unroll
            for (int c = 0; c < 4; ++c) d[mi][nj][c] = 0.f;

    const int niters = K >> 6;
    const int lrow = tid >> 3;
    const int lseg = tid & 7;
    const int a_row = wm * 64 + (lane & 15);
    const int a_cb  = (lane >> 4) * 16;
    const int b_row = wn * 64 + (lane & 7) + ((lane >> 4) << 3);
    const int b_cb  = ((lane >> 3) & 1) * 16;

    auto issue_loads = [&](int it, int st) {
        const int k0 = it << 6;
        uint32_t sA = sb + st * 16384;
        uint32_t sB = sb + SM_B_OFF + st * 16384;
        #pragma unroll
        for (int i = 0; i < 8; ++i) {
            int row = lrow + i * 16;
            uint32_t so = swz(row * 128 + lseg * 16);
            cp16(sA + so, Ah  + (size_t)(b0 + row) * K + k0 + lseg * 8);
            cp16(sB + so, Bth + (size_t)(ncol0 + row) * K + k0 + lseg * 8);
        }
        CP_COMMIT();
    };

    issue_loads(0, 0);
    if (niters > 1) issue_loads(1, 1);

    int cur = 0;
    for (int it = 0; it < niters; ++it) {
        if (it == niters - 1) { CP_WAIT(0); } else { CP_WAIT(1); }
        __syncthreads();
        if (it + 2 < niters) {
            int nx = cur + 2; if (nx >= 3) nx -= 3;
            issue_loads(it + 2, nx);
        }

        uint32_t sA = sb + cur * 16384;
        uint32_t sB = sb + SM_B_OFF + cur * 16384;
        #pragma unroll
        for (int ks = 0; ks < 4; ++ks) {
            uint32_t afr[4][4], bfr[4][4];
            #pragma unroll
            for (int mi = 0; mi < 4; ++mi)
                ldm_x4(afr[mi], sA + swz((a_row + mi * 16) * 128 + ks * 32 + a_cb));
            #pragma unroll
            for (int nj2 = 0; nj2 < 4; ++nj2)
                ldm_x4(bfr[nj2], sB + swz((b_row + nj2 * 16) * 128 + ks * 32 + b_cb));
            #pragma unroll
            for (int mi = 0; mi < 4; ++mi)
                #pragma unroll
                for (int nj = 0; nj < 8; ++nj)
                    mma16816(d[mi][nj], afr[mi], &bfr[nj >> 1][(nj & 1) * 2]);
        }
        cur = (cur == 2) ? 0 : cur + 1;
    }

    // ---- epilogue: act + Wo dot; warp's 64 cols == one neuron, fully in-warp ----
    {
        const int g = lane >> 2, i = lane & 3;
        const float* bs = (const float*)(smem + SM_BIAS) + wn * 64;
        const float* ws = (const float*)(smem + SM_WO)   + wn * 64;
        const int neuron = blockIdx.y * 2 + wn;
        const float bon = bo[neuron];

        #pragma unroll
        for (int mi = 0; mi < 4; ++mi) {
            float p0 = 0.f, p1 = 0.f;
            #pragma unroll
            for (int nj = 0; nj < 8; ++nj) {
                int c = nj * 8 + 2 * i;
                float w0 = ws[c], w1 = ws[c + 1];
                float bb0 = bs[c], bb1 = bs[c + 1];
                p0 += liquid_act(d[mi][nj][0] + bb0) * w0 + liquid_act(d[mi][nj][1] + bb1) * w1;
                p1 += liquid_act(d[mi][nj][2] + bb0) * w0 + liquid_act(d[mi][nj][3] + bb1) * w1;
            }
            p0 += __shfl_xor_sync(0xffffffffu, p0, 1);
            p0 += __shfl_xor_sync(0xffffffffu, p0, 2);
            p1 += __shfl_xor_sync(0xffffffffu, p1, 1);
            p1 += __shfl_xor_sync(0xffffffffu, p1, 2);
            if (i == 0) {
                int r = b0 + wm * 64 + mi * 16 + g;
                preh[(size_t)r * Nn + neuron]       = __float2half(p0 + bon);
                preh[(size_t)(r + 8) * Nn + neuron] = __float2half(p1 + bon);
            }
        }
    }
}

// ---------------- lateral GEMM (layers 0,1): hh[b][n] = sum_m preh[b][m]*La[m][n] ----------------
// BM=64 for grid coverage: grid (BATCH/64, N/64) = 256/128 CTAs.
// 128 threads = 4 warps, warp tile 32x32 (wm: rows 32wm, wn: cols 32wn).
// smem: A stages @0 (3x8KB); B stages @24576 (3x8KB) = 49152.
#define LSM_B_OFF 24576
#define LSM_TOTAL 49152
__global__ void __launch_bounds__(128, 2)
lat_mma_kernel(const __half* __restrict__ preh, const __half* __restrict__ Lat,
               __half* __restrict__ hh, int N)
{
    extern __shared__ char smem[];
    const uint32_t sb = smem_u32(smem);
    const int tid = threadIdx.x;
    const int wid  = tid >> 5;
    const int lane = tid & 31;
    const int wm = wid >> 1;          // 0-1: rows wm*32
    const int wn = wid & 1;           // 0-1: cols wn*32
    const int b0 = blockIdx.x * 64;
    const int c0 = blockIdx.y * 64;

    float d[2][4][4];
    #pragma unroll
    for (int mi = 0; mi < 2; ++mi)
        #pragma unroll
        for (int nj = 0; nj < 4; ++nj)
            #pragma unroll
            for (int c = 0; c < 4; ++c) d[mi][nj][c] = 0.f;

    const int niters = N >> 6;
    const int a_row = wm * 32 + (lane & 15);
    const int a_cb  = (lane >> 4) * 16;
    const int b_row = wn * 32 + (lane & 7) + ((lane >> 4) << 3);
    const int b_cb  = ((lane >> 3) & 1) * 16;

    auto issue_loads = [&](int it, int st) {
        const int k0 = it << 6;
        uint32_t sA = sb + st * 8192;
        uint32_t sB = sb + LSM_B_OFF + st * 8192;
        #pragma unroll
        for (int i = 0; i < 4; ++i) {
            int c = tid + i * 128;          // 0..511
            int row = c >> 3, seg = c & 7;
            uint32_t so = swz(row * 128 + seg * 16);
            cp16(sA + so, preh + (size_t)(b0 + row) * N + k0 + seg * 8);
            cp16(sB + so, Lat  + (size_t)(c0 + row) * N + k0 + seg * 8);
        }
        CP_COMMIT();
    };

    issue_loads(0, 0);
    if (niters > 1) issue_loads(1, 1);

    int cur = 0;
    for (int it = 0; it < niters; ++it) {
        if (it == niters - 1) { CP_WAIT(0); } else { CP_WAIT(1); }
        __syncthreads();
        if (it + 2 < niters) {
            int nx = cur + 2; if (nx >= 3) nx -= 3;
            issue_loads(it + 2, nx);
        }

        uint32_t sA = sb + cur * 8192;
        uint32_t sB = sb + LSM_B_OFF + cur * 8192;
        #pragma unroll
        for (int ks = 0; ks < 4; ++ks) {
            uint32_t afr[2][4], bfr[2][4];
            #pragma unroll
            for (int mi = 0; mi < 2; ++mi)
                ldm_x4(afr[mi], sA + swz((a_row + mi * 16) * 128 + ks * 32 + a_cb));
            #pragma unroll
            for (int nj2 = 0; nj2 < 2; ++nj2)
                ldm_x4(bfr[nj2], sB + swz((b_row + nj2 * 16) * 128 + ks * 32 + b_cb));
            #pragma unroll
            for (int mi = 0; mi < 2; ++mi)
                #pragma unroll
                for (int nj = 0; nj < 4; ++nj)
                    mma16816(d[mi][nj], afr[mi], &bfr[nj >> 1][(nj & 1) * 2]);
        }
        cur = (cur == 2) ? 0 : cur + 1;
    }

    // epilogue: write hh (fp16)
    {
        const int g = lane >> 2, i = lane & 3;
        #pragma unroll
        for (int mi = 0; mi < 2; ++mi) {
            #pragma unroll
            for (int nj = 0; nj < 4; ++nj) {
                int c = c0 + wn * 32 + nj * 8 + 2 * i;
                int r = b0 + wm * 32 + mi * 16 + g;
                *(__half2*)(hh + (size_t)r * N + c) = __floats2half2_rn(d[mi][nj][0], d[mi][nj][1]);
                *(__half2*)(hh + (size_t)(r + 8) * N + c) = __floats2half2_rn(d[mi][nj][2], d[mi][nj][3]);
            }
        }
    }
}

// ---------------- merged preprocessing: wsplit + latprep(0,1) + xsplit + M2 ----------------
__global__ __launch_bounds__(256)
void prep_all_kernel(const float* __restrict__ Wi0, const float* __restrict__ Wi1,
                     const float* __restrict__ Wi2, __half* __restrict__ wth,
                     const float* __restrict__ L0, const float* __restrict__ a0,
                     const float* __restrict__ L1, const float* __restrict__ a1,
                     __half* __restrict__ lat,
                     const float* __restrict__ L2, const float* __restrict__ a2,
                     const float* __restrict__ Wout, float* __restrict__ m2,
                     const float* __restrict__ x, __half* __restrict__ xh)
{
    int b = blockIdx.x;
    if (b < 2688) {
        const float* Wi; __half* dst; int K, n, kc;
        if (b < 2048)      { Wi = Wi0; dst = wth;            K = 512; kc = b & 7; n = b >> 3; }
        else if (b < 2560) { b -= 2048; Wi = Wi1; dst = wth + 8388608;  K = 256; kc = b & 3; n = b >> 2; }
        else               { b -= 2560; Wi = Wi2; dst = wth + 10485760; K = 128; kc = b & 1; n = b >> 1; }
        const int k0 = kc * 64;
        __shared__ float tile[64][65];
        const float* src = Wi + ((size_t)n * K + k0) * SDIM;
        for (int i = threadIdx.x; i < 4096; i += 256) {
            int kk = i >> 6, s = i & 63;
            tile[kk][s] = src[kk * SDIM + s];
        }
        __syncthreads();
        for (int i = threadIdx.x; i < 4096; i += 256) {
            int s = i >> 6, kk = i & 63;
            dst[(size_t)n * SDIM * K + (size_t)s * K + k0 + kk] = __float2half(tile[kk][s]);
        }
    } else if (b < 3008) {
        b -= 2688;
        const float* L; const float* a; __half* dst; int N;
        if (b < 256) { L = L0; a = a0; dst = lat;         N = 256; }
        else         { b -= 256; L = L1; a = a1; dst = lat + 65536; N = 128; }
        int e = b * 256 + threadIdx.x;
        int n = e / N, k = e - n * N;
        float v = 0.1f * L[(size_t)k * N + n] * a[n];
        if (k == n) v += a[n];
        dst[e] = __float2half(v);
    } else if (b < 5056) {
        int i = (b - 3008) * 256 + threadIdx.x;
        float4 v = ((const float4*)x)[i];
        ((__half2*)xh)[2 * i]     = __floats2half2_rn(v.x, v.y);
        ((__half2*)xh)[2 * i + 1] = __floats2half2_rn(v.z, v.w);
    } else {
        for (int e = threadIdx.x; e < 64 * OUTD; e += 256) {
            int m = e / OUTD, o = e - m * OUTD;
            float s = a2[m] * Wout[m * OUTD + o];
            #pragma unroll 4
            for (int n = 0; n < 64; ++n)
                s += 0.1f * L2[(size_t)m * 64 + n] * a2[n] * Wout[n * OUTD + o];
            m2[e] = s;
        }
    }
}

// ---------------- final projection: y = preh2 @ M2 + bout ----------------
__global__ __launch_bounds__(256)
void out_kernel(const __half* __restrict__ preh, const float* __restrict__ m2,
                const float* __restrict__ bout, float* __restrict__ y)
{
    int idx = blockIdx.x * blockDim.x + threadIdx.x;
    if (idx >= BATCH * OUTD) return;
    int b = idx / OUTD;
    int o = idx - b * OUTD;
    const __half* pb = preh + (size_t)b * 64;
    float s = bout[o];
    #pragma unroll
    for (int m = 0; m < 64; ++m)
        s += __half2float(pb[m]) * m2[m * OUTD + o];
    y[idx] = s;
}

extern "C" void kernel_launch(void* const* d_in, const int* in_sizes, int n_in,
                              void* d_out, int out_size)
{
    (void)in_sizes; (void)n_in; (void)out_size;
    const float* x = (const float*)d_in[0];
    const float *Wi[3], *bi[3], *bl[3], *Wo[3], *bo[3], *Lm[3], *ad[3];
    for (int l = 0; l < 3; ++l) {
        int base = 1 + 7 * l;
        Wi[l] = (const float*)d_in[base + 0];
        bi[l] = (const float*)d_in[base + 1];
        bl[l] = (const float*)d_in[base + 2];
        Wo[l] = (const float*)d_in[base + 3];
        bo[l] = (const float*)d_in[base + 4];
        Lm[l] = (const float*)d_in[base + 5];
        ad[l] = (const float*)d_in[base + 6];
    }
    const float* Wout = (const float*)d_in[22];
    const float* bout = (const float*)d_in[23];

    __half *ah, *wth, *preh, *lat;
    float *m2;
    cudaGetSymbolAddress((void**)&ah,   g_ah);
    cudaGetSymbolAddress((void**)&wth,  g_wth);
    cudaGetSymbolAddress((void**)&preh, g_preh);
    cudaGetSymbolAddress((void**)&lat,  g_lat);
    cudaGetSymbolAddress((void**)&m2,   g_m2);

    cudaFuncSetAttribute(liquid_mma_kernel, cudaFuncAttributeMaxDynamicSharedMemorySize, SM_TOTAL);
    cudaFuncSetAttribute(lat_mma_kernel, cudaFuncAttributeMaxDynamicSharedMemorySize, LSM_TOTAL);

    const int Ns[3] = {256, 128, 64};
    const int Ks[3] = {512, 256, 128};
    const size_t woff[3] = {0, 8388608, 10485760};
    const size_t loff[2] = {0, 65536};

    prep_all_kernel<<<5057, 256>>>(Wi[0], Wi[1], Wi[2], wth,
                                   Lm[0], ad[0], Lm[1], ad[1], lat,
                                   Lm[2], ad[2], Wout, m2, x, ah);

    for (int l = 0; l < 3; ++l) {
        dim3 grid(BATCH / BM, (Ns[l] * SDIM) / BN);   // = Ns[l]/2
        liquid_mma_kernel<<<grid, 128, SM_TOTAL>>>(ah, wth + woff[l],
                                                   bi[l], bl[l], Wo[l], bo[l], preh,
                                                   Ks[l], Ns[l]);
        if (l < 2) {
            dim3 lgrid(BATCH / 64, Ns[l] / 64);
            lat_mma_kernel<<<lgrid, 128, LSM_TOTAL>>>(preh, lat + loff[l], ah, Ns[l]);
        }
    }
    out_kernel<<<(BATCH * OUTD + 255) / 256, 256>>>(preh, m2, bout, (float*)d_out);
}